// round 1
// baseline (speedup 1.0000x reference)
#include <cuda_runtime.h>
#include <math.h>

typedef unsigned long long u64;

#define S_LEN 4096
#define B_SZ  2
#define DM    1024
#define NH    16
#define DK    64
#define RAD   8
#define WINW  9
#define M_TOT (B_SZ * S_LEN)
#define QT    64

// Scratch (device globals: allocation-free per harness rules)
__device__ float g_Q[M_TOT * DM];
__device__ float g_K[M_TOT * DM];
__device__ float g_V[M_TOT * DM];
__device__ float g_A[M_TOT * DM];

// ---- packed f32x2 helpers (FFMA2 path: 2x fp32 throughput on sm_103a) ----
__device__ __forceinline__ u64 ffma2(u64 a, u64 b, u64 c) {
    u64 d;
    asm("fma.rn.f32x2 %0, %1, %2, %3;" : "=l"(d) : "l"(a), "l"(b), "l"(c));
    return d;
}
__device__ __forceinline__ u64 pack_dup(float f) {
    u64 r;
    asm("mov.b64 %0, {%1, %1};" : "=l"(r) : "f"(f));
    return r;
}
__device__ __forceinline__ float2 unpack2(u64 v) {
    float2 r;
    asm("mov.b64 {%0, %1}, %2;" : "=f"(r.x), "=f"(r.y) : "l"(v));
    return r;
}

// ---- 128x128x8 fp32 GEMM, inner product entirely in FFMA2 ----
#define BM 128
#define BN 128
#define BK 8

__global__ __launch_bounds__(256, 2)
void sgemm_kernel(const float* __restrict__ A, const float* __restrict__ B,
                  float* __restrict__ C, int M, int N, int K) {
    __shared__ __align__(16) u64   Asd[BK][BM];  // A values pair-duplicated
    __shared__ __align__(16) float Bs[BK][BN];

    int tid = threadIdx.x;
    int bm = blockIdx.y * BM;
    int bn = blockIdx.x * BN;
    int tx = tid & 15, ty = tid >> 4;

    int a_row = tid >> 1;            // 0..127
    int a_col = (tid & 1) * 4;       // 0 or 4
    int b_row = tid >> 5;            // 0..7
    int b_col = (tid & 31) * 4;      // 0..124

    const float* Ap = A + (size_t)(bm + a_row) * K + a_col;
    const float* Bp = B + (size_t)b_row * N + bn + b_col;

    u64 acc[8][4];
#pragma unroll
    for (int i = 0; i < 8; i++)
#pragma unroll
        for (int j = 0; j < 4; j++) acc[i][j] = 0ULL;

    float4 ag = *(const float4*)(Ap);
    float4 bg = *(const float4*)(Bp);

    for (int k0 = 0; k0 < K; k0 += BK) {
        Asd[a_col + 0][a_row] = pack_dup(ag.x);
        Asd[a_col + 1][a_row] = pack_dup(ag.y);
        Asd[a_col + 2][a_row] = pack_dup(ag.z);
        Asd[a_col + 3][a_row] = pack_dup(ag.w);
        *(float4*)&Bs[b_row][b_col] = bg;
        __syncthreads();

        if (k0 + BK < K) {  // prefetch next tile (LDG overlapped with compute)
            ag = *(const float4*)(Ap + k0 + BK);
            bg = *(const float4*)(Bp + (size_t)(k0 + BK) * N);
        }

#pragma unroll
        for (int kk = 0; kk < BK; kk++) {
            u64 a2[8], b2[4];
            ulonglong2 t0 = *(const ulonglong2*)&Asd[kk][ty * 8 + 0];
            ulonglong2 t1 = *(const ulonglong2*)&Asd[kk][ty * 8 + 2];
            ulonglong2 t2 = *(const ulonglong2*)&Asd[kk][ty * 8 + 4];
            ulonglong2 t3 = *(const ulonglong2*)&Asd[kk][ty * 8 + 6];
            a2[0] = t0.x; a2[1] = t0.y; a2[2] = t1.x; a2[3] = t1.y;
            a2[4] = t2.x; a2[5] = t2.y; a2[6] = t3.x; a2[7] = t3.y;
            ulonglong2 u0 = *(const ulonglong2*)&Bs[kk][tx * 8];
            ulonglong2 u1 = *(const ulonglong2*)&Bs[kk][tx * 8 + 4];
            b2[0] = u0.x; b2[1] = u0.y; b2[2] = u1.x; b2[3] = u1.y;
#pragma unroll
            for (int i = 0; i < 8; i++)
#pragma unroll
                for (int j = 0; j < 4; j++)
                    acc[i][j] = ffma2(a2[i], b2[j], acc[i][j]);
        }
        __syncthreads();
    }

    float* Cp = C + (size_t)(bm + ty * 8) * N + bn + tx * 8;
#pragma unroll
    for (int i = 0; i < 8; i++) {
        float2 p0 = unpack2(acc[i][0]);
        float2 p1 = unpack2(acc[i][1]);
        float2 p2 = unpack2(acc[i][2]);
        float2 p3 = unpack2(acc[i][3]);
        *(float4*)(Cp + (size_t)i * N)     = make_float4(p0.x, p0.y, p1.x, p1.y);
        *(float4*)(Cp + (size_t)i * N + 4) = make_float4(p2.x, p2.y, p3.x, p3.y);
    }
}

// ---- windowed causal attention: 9-wide window, warp-per-query ----
__global__ __launch_bounds__(256)
void attn_kernel(const float* __restrict__ Q, const float* __restrict__ K,
                 const float* __restrict__ V, float* __restrict__ O) {
    int qbase = blockIdx.x * QT;
    int h = blockIdx.y;
    int b = blockIdx.z;

    __shared__ __align__(16) float Ks[QT + RAD][DK];
    __shared__ __align__(16) float Vs[QT + RAD][DK];

    int tid = threadIdx.x;
    const size_t bh = (size_t)b * S_LEN * DM + (size_t)h * DK;
    int base = qbase - RAD;

    // stage K/V window [qbase-8, qbase+63] into smem
    for (int idx = tid; idx < (QT + RAD) * (DK / 4); idx += blockDim.x) {
        int r = idx / (DK / 4);
        int c = (idx % (DK / 4)) * 4;
        int j = base + r;
        float4 kv = make_float4(0.f, 0.f, 0.f, 0.f), vv = kv;
        if (j >= 0) {
            kv = *(const float4*)(K + bh + (size_t)j * DM + c);
            vv = *(const float4*)(V + bh + (size_t)j * DM + c);
        }
        *(float4*)&Ks[r][c] = kv;
        *(float4*)&Vs[r][c] = vv;
    }
    __syncthreads();

    int warp = tid >> 5, lane = tid & 31;
    const float scale = 1.0f / 0.56f;   // 1/(2T), T=0.28

    for (int qi = 0; qi < QT / 8; qi++) {
        int sl = warp * (QT / 8) + qi;   // local query index 0..63
        int s = qbase + sl;
        float q0 = Q[bh + (size_t)s * DM + lane];
        float q1 = Q[bh + (size_t)s * DM + lane + 32];

        float sc[WINW];
#pragma unroll
        for (int w = 0; w < WINW; w++) {
            int r = sl + w;   // smem row of key position s-RAD+w
            float p = q0 * Ks[r][lane] + q1 * Ks[r][lane + 32];
#pragma unroll
            for (int o = 16; o > 0; o >>= 1)
                p += __shfl_xor_sync(0xffffffffu, p, o);
            sc[w] = (s - RAD + w >= 0) ? p * scale : -INFINITY;
        }

        float m = sc[0];
#pragma unroll
        for (int w = 1; w < WINW; w++) m = fmaxf(m, sc[w]);

        float sum = 0.f, a0 = 0.f, a1 = 0.f;
#pragma unroll
        for (int w = 0; w < WINW; w++) {
            float e = __expf(sc[w] - m);
            sum += e;
            int r = sl + w;
            a0 += e * Vs[r][lane];
            a1 += e * Vs[r][lane + 32];
        }
        float inv = 1.0f / sum;
        O[bh + (size_t)s * DM + lane]      = a0 * inv;
        O[bh + (size_t)s * DM + lane + 32] = a1 * inv;
    }
}

extern "C" void kernel_launch(void* const* d_in, const int* in_sizes, int n_in,
                              void* d_out, int out_size) {
    const float* x  = (const float*)d_in[0];
    const float* Wq = (const float*)d_in[1];
    const float* Wk = (const float*)d_in[2];
    const float* Wv = (const float*)d_in[3];
    const float* Wo = (const float*)d_in[4];
    float* out = (float*)d_out;

    float *pQ, *pK, *pV, *pA;
    cudaGetSymbolAddress((void**)&pQ, g_Q);
    cudaGetSymbolAddress((void**)&pK, g_K);
    cudaGetSymbolAddress((void**)&pV, g_V);
    cudaGetSymbolAddress((void**)&pA, g_A);

    dim3 g(DM / BN, M_TOT / BM), blk(256);
    sgemm_kernel<<<g, blk>>>(x, Wq, pQ, M_TOT, DM, DM);
    sgemm_kernel<<<g, blk>>>(x, Wk, pK, M_TOT, DM, DM);
    sgemm_kernel<<<g, blk>>>(x, Wv, pV, M_TOT, DM, DM);

    dim3 ga(S_LEN / QT, NH, B_SZ);
    attn_kernel<<<ga, 256>>>(pQ, pK, pV, pA);

    sgemm_kernel<<<g, blk>>>(pA, Wo, out, M_TOT, DM, DM);
}

// round 6
// speedup vs baseline: 2.7645x; 2.7645x over previous
#include <cuda_runtime.h>
#include <cuda_fp16.h>
#include <math.h>
#include <stdint.h>

typedef uint32_t u32; typedef uint64_t u64;

#define S_LEN 4096
#define B_SZ  2
#define DM    1024
#define NH    16
#define DK    64
#define RAD   8
#define WINW  9
#define M_TOT (B_SZ * S_LEN)
#define QT    64

// ---------------- scratch (device globals: allocation-free) ----------------
__device__ __half g_Xhi[M_TOT * DM], g_Xlo[M_TOT * DM];   // x split, [m][k]
__device__ __half g_Ahi[M_TOT * DM], g_Alo[M_TOT * DM];   // attn out split, [m][k]
__device__ __half g_Whi[4][DM * DM], g_Wlo[4][DM * DM];   // W^T split, [n][k]
__device__ float  g_Q[M_TOT * DM], g_K[M_TOT * DM], g_V[M_TOT * DM];

// ---------------- fp16x3 tensor-core GEMM ----------------
// C[M,N] = (Ahi+Alo)[m][k] @ (Bhi+Blo)[n][k]^T, fp32 accumulate, lo*lo dropped.
#define BM 128
#define BN 128
#define BK 64
#define NSTG 3
#define PLANE_B (128 * 128)          // bytes per plane per stage (128 rows x 128B)
#define STG_B   (4 * PLANE_B)        // Ahi,Alo,Bhi,Blo = 64 KB
#define DYN_SMEM (NSTG * STG_B)      // 192 KB

__device__ __forceinline__ void cp16(u32 dst, const void* src) {
    asm volatile("cp.async.cg.shared.global [%0], [%1], 16;" :: "r"(dst), "l"(src) : "memory");
}

#define LDMX4(r, addr)                                                        \
    asm volatile("ldmatrix.sync.aligned.m8n8.x4.shared.b16 {%0,%1,%2,%3}, [%4];" \
                 : "=r"((r)[0]), "=r"((r)[1]), "=r"((r)[2]), "=r"((r)[3])     \
                 : "r"(addr))

#define MMA16(c, a, b)                                                        \
    asm volatile("mma.sync.aligned.m16n8k16.row.col.f32.f16.f16.f32 "         \
                 "{%0,%1,%2,%3}, {%4,%5,%6,%7}, {%8,%9}, {%0,%1,%2,%3};"      \
                 : "+f"((c)[0]), "+f"((c)[1]), "+f"((c)[2]), "+f"((c)[3])     \
                 : "r"((a)[0]), "r"((a)[1]), "r"((a)[2]), "r"((a)[3]),        \
                   "r"((b)[0]), "r"((b)[1]))

__global__ __launch_bounds__(256, 1)
void gemm_fp16x3(const __half* __restrict__ Ahi, const __half* __restrict__ Alo,
                 const __half* __restrict__ Bhi, const __half* __restrict__ Blo,
                 float* __restrict__ C) {
    extern __shared__ char smc[];
    const u32 s0 = (u32)__cvta_generic_to_shared(smc);
    const int tid = threadIdx.x, wid = tid >> 5, lane = tid & 31;
    const int wm = wid & 1, wn = wid >> 1;              // 2x4 warp grid: 64x32 per warp
    const int m0 = blockIdx.y * BM, n0 = blockIdx.x * BN;
    const int g = lane >> 2, tg = lane & 3;

    // cp.async plan: 4096 16B units/stage, 16 per thread.
    // unit u: plane = u>>10, row = (u>>3)&127, chunk c = u&7; swizzle c^(row&7).
    u32 sdst[16]; const char* gsrc[16];
#pragma unroll
    for (int t = 0; t < 16; t++) {
        int u = tid + t * 256;
        int plane = u >> 10, row = (u >> 3) & 127, c = u & 7;
        sdst[t] = s0 + plane * PLANE_B + row * 128 + ((c ^ (row & 7)) * 16);
        const __half* bp = (plane == 0) ? Ahi : (plane == 1) ? Alo
                          : (plane == 2) ? Bhi : Blo;
        int grow = ((plane < 2) ? m0 : n0) + row;
        gsrc[t] = (const char*)(bp + (size_t)grow * DM) + c * 16;
    }

#define ISSUE(kidx) do {                                                      \
    u32 so = ((kidx) % NSTG) * STG_B;                                         \
    _Pragma("unroll")                                                         \
    for (int t = 0; t < 16; t++)                                              \
        cp16(sdst[t] + so, gsrc[t] + (size_t)(kidx) * 128);                   \
    asm volatile("cp.async.commit_group;" ::: "memory");                      \
} while (0)

    ISSUE(0); ISSUE(1); ISSUE(2);

    float acc[4][4][4];
#pragma unroll
    for (int i = 0; i < 4; i++)
#pragma unroll
        for (int j = 0; j < 4; j++)
#pragma unroll
            for (int q = 0; q < 4; q++) acc[i][j][q] = 0.f;

    const int NIT = DM / BK;                            // 16
    const int rsel = lane & 15, csel = lane >> 4;

    for (int it = 0; it < NIT; it++) {
        asm volatile("cp.async.wait_group 2;" ::: "memory");
        __syncthreads();
        const u32 sb = s0 + (it % NSTG) * STG_B;

#pragma unroll
        for (int j = 0; j < 4; j++) {                   // four k16 steps per BK=64
            u32 ahi[4][4], alo[4][4], bhi[4][2], blo[4][2];
#pragma unroll
            for (int mt = 0; mt < 4; mt++) {
                int row = wm * 64 + mt * 16 + rsel;
                u32 ad = sb + row * 128 + (((2 * j + csel) ^ (row & 7)) * 16);
                LDMX4(ahi[mt], ad);
                LDMX4(alo[mt], ad + PLANE_B);
            }
#pragma unroll
            for (int np = 0; np < 2; np++) {            // each x4 covers two n8 tiles
                int row = wn * 32 + np * 16 + rsel;
                u32 bd = sb + 2 * PLANE_B + row * 128 + (((2 * j + csel) ^ (row & 7)) * 16);
                u32 r[4];
                LDMX4(r, bd);
                bhi[2*np][0] = r[0]; bhi[2*np+1][0] = r[1];
                bhi[2*np][1] = r[2]; bhi[2*np+1][1] = r[3];
                LDMX4(r, bd + PLANE_B);
                blo[2*np][0] = r[0]; blo[2*np+1][0] = r[1];
                blo[2*np][1] = r[2]; blo[2*np+1][1] = r[3];
            }
#pragma unroll
            for (int mt = 0; mt < 4; mt++)
#pragma unroll
                for (int nt = 0; nt < 4; nt++) {
                    MMA16(acc[mt][nt], ahi[mt], bhi[nt]);
                    MMA16(acc[mt][nt], ahi[mt], blo[nt]);
                    MMA16(acc[mt][nt], alo[mt], bhi[nt]);
                }
        }
        __syncthreads();
        if (it + 3 < NIT) ISSUE(it + 3);
        else asm volatile("cp.async.commit_group;" ::: "memory");
    }

#pragma unroll
    for (int mt = 0; mt < 4; mt++)
#pragma unroll
        for (int nt = 0; nt < 4; nt++) {
            int row = m0 + wm * 64 + mt * 16 + g;
            int col = n0 + wn * 32 + nt * 8 + 2 * tg;
            float* p = C + (size_t)row * DM + col;
            *(float2*)p = make_float2(acc[mt][nt][0], acc[mt][nt][1]);
            *(float2*)(p + 8 * DM) = make_float2(acc[mt][nt][2], acc[mt][nt][3]);
        }
#undef ISSUE
}

// ---------------- x split: [m][k] fp32 -> hi/lo fp16 planes ----------------
__global__ void split_x_k(const float* __restrict__ in,
                          __half* __restrict__ hi, __half* __restrict__ lo) {
    int i = blockIdx.x * blockDim.x + threadIdx.x;
    float4 v = ((const float4*)in)[i];
    __half h0 = __float2half_rn(v.x), h1 = __float2half_rn(v.y);
    __half h2 = __float2half_rn(v.z), h3 = __float2half_rn(v.w);
    ((__half2*)hi)[2 * i]     = __halves2half2(h0, h1);
    ((__half2*)hi)[2 * i + 1] = __halves2half2(h2, h3);
    __half l0 = __float2half_rn(v.x - __half2float(h0));
    __half l1 = __float2half_rn(v.y - __half2float(h1));
    __half l2 = __float2half_rn(v.z - __half2float(h2));
    __half l3 = __float2half_rn(v.w - __half2float(h3));
    ((__half2*)lo)[2 * i]     = __halves2half2(l0, l1);
    ((__half2*)lo)[2 * i + 1] = __halves2half2(l2, l3);
}

// ---------------- W transpose + split: W[k][n] -> hi/lo [n][k] ----------------
__global__ void transpose_split_k(const float* __restrict__ W,
                                  __half* __restrict__ hi, __half* __restrict__ lo) {
    __shared__ float t[32][33];
    int bx = blockIdx.x * 32, by = blockIdx.y * 32;
    int x = threadIdx.x, y = threadIdx.y;
#pragma unroll
    for (int j = 0; j < 32; j += 8)
        t[y + j][x] = W[(size_t)(by + y + j) * DM + bx + x];
    __syncthreads();
#pragma unroll
    for (int j = 0; j < 32; j += 8) {
        float v = t[x][y + j];
        __half h = __float2half_rn(v);
        size_t o = (size_t)(bx + y + j) * DM + by + x;
        hi[o] = h;
        lo[o] = __float2half_rn(v - __half2float(h));
    }
}

// ---------------- windowed causal attention; epilogue splits to fp16 planes ----------------
__global__ __launch_bounds__(256)
void attn_kernel(const float* __restrict__ Q, const float* __restrict__ K,
                 const float* __restrict__ V,
                 __half* __restrict__ Ohi, __half* __restrict__ Olo) {
    int qbase = blockIdx.x * QT;
    int h = blockIdx.y;
    int b = blockIdx.z;

    __shared__ __align__(16) float Ks[QT + RAD][DK];
    __shared__ __align__(16) float Vs[QT + RAD][DK];

    int tid = threadIdx.x;
    const size_t bh = (size_t)b * S_LEN * DM + (size_t)h * DK;
    int base = qbase - RAD;

    for (int idx = tid; idx < (QT + RAD) * (DK / 4); idx += blockDim.x) {
        int r = idx / (DK / 4);
        int cidx = (idx % (DK / 4)) * 4;
        int j = base + r;
        float4 kv = make_float4(0.f, 0.f, 0.f, 0.f), vv = kv;
        if (j >= 0) {
            kv = *(const float4*)(K + bh + (size_t)j * DM + cidx);
            vv = *(const float4*)(V + bh + (size_t)j * DM + cidx);
        }
        *(float4*)&Ks[r][cidx] = kv;
        *(float4*)&Vs[r][cidx] = vv;
    }
    __syncthreads();

    int warp = tid >> 5, lane = tid & 31;
    const float scale = 1.0f / 0.56f;   // 1/(2T), T=0.28

    for (int qi = 0; qi < QT / 8; qi++) {
        int sl = warp * (QT / 8) + qi;
        int s = qbase + sl;
        float q0 = Q[bh + (size_t)s * DM + lane];
        float q1 = Q[bh + (size_t)s * DM + lane + 32];

        float sc[WINW];
#pragma unroll
        for (int w = 0; w < WINW; w++) {
            int r = sl + w;
            float p = q0 * Ks[r][lane] + q1 * Ks[r][lane + 32];
#pragma unroll
            for (int o = 16; o > 0; o >>= 1)
                p += __shfl_xor_sync(0xffffffffu, p, o);
            sc[w] = (s - RAD + w >= 0) ? p * scale : -INFINITY;
        }

        float m = sc[0];
#pragma unroll
        for (int w = 1; w < WINW; w++) m = fmaxf(m, sc[w]);

        float sum = 0.f, a0 = 0.f, a1 = 0.f;
#pragma unroll
        for (int w = 0; w < WINW; w++) {
            float e = __expf(sc[w] - m);
            sum += e;
            int r = sl + w;
            a0 += e * Vs[r][lane];
            a1 += e * Vs[r][lane + 32];
        }
        float inv = 1.0f / sum;
        float o0 = a0 * inv, o1 = a1 * inv;
        size_t i0 = bh + (size_t)s * DM + lane;
        size_t i1 = i0 + 32;
        __half h0 = __float2half_rn(o0);
        __half h1 = __float2half_rn(o1);
        Ohi[i0] = h0; Olo[i0] = __float2half_rn(o0 - __half2float(h0));
        Ohi[i1] = h1; Olo[i1] = __float2half_rn(o1 - __half2float(h1));
    }
}

// ---------------- launch ----------------
extern "C" void kernel_launch(void* const* d_in, const int* in_sizes, int n_in,
                              void* d_out, int out_size) {
    const float* x  = (const float*)d_in[0];
    const float* Wq = (const float*)d_in[1];
    const float* Wk = (const float*)d_in[2];
    const float* Wv = (const float*)d_in[3];
    const float* Wo = (const float*)d_in[4];
    float* out = (float*)d_out;

    __half *pXhi, *pXlo, *pAhi, *pAlo, *pWhi, *pWlo;
    float *pQ, *pK, *pV;
    cudaGetSymbolAddress((void**)&pXhi, g_Xhi);
    cudaGetSymbolAddress((void**)&pXlo, g_Xlo);
    cudaGetSymbolAddress((void**)&pAhi, g_Ahi);
    cudaGetSymbolAddress((void**)&pAlo, g_Alo);
    cudaGetSymbolAddress((void**)&pWhi, g_Whi);
    cudaGetSymbolAddress((void**)&pWlo, g_Wlo);
    cudaGetSymbolAddress((void**)&pQ, g_Q);
    cudaGetSymbolAddress((void**)&pK, g_K);
    cudaGetSymbolAddress((void**)&pV, g_V);

    cudaFuncSetAttribute(gemm_fp16x3, cudaFuncAttributeMaxDynamicSharedMemorySize, DYN_SMEM);

    split_x_k<<<(M_TOT * DM / 4) / 256, 256>>>(x, pXhi, pXlo);

    dim3 tg(DM / 32, DM / 32), tb(32, 8);
    const float* Ws[4] = {Wq, Wk, Wv, Wo};
    for (int i = 0; i < 4; i++)
        transpose_split_k<<<tg, tb>>>(Ws[i], pWhi + (size_t)i * DM * DM,
                                      pWlo + (size_t)i * DM * DM);

    dim3 gg(DM / BN, M_TOT / BM);
    gemm_fp16x3<<<gg, 256, DYN_SMEM>>>(pXhi, pXlo, pWhi + 0 * (size_t)DM * DM,
                                       pWlo + 0 * (size_t)DM * DM, pQ);
    gemm_fp16x3<<<gg, 256, DYN_SMEM>>>(pXhi, pXlo, pWhi + 1 * (size_t)DM * DM,
                                       pWlo + 1 * (size_t)DM * DM, pK);
    gemm_fp16x3<<<gg, 256, DYN_SMEM>>>(pXhi, pXlo, pWhi + 2 * (size_t)DM * DM,
                                       pWlo + 2 * (size_t)DM * DM, pV);

    dim3 ga(S_LEN / QT, NH, B_SZ);
    attn_kernel<<<ga, 256>>>(pQ, pK, pV, pAhi, pAlo);

    gemm_fp16x3<<<gg, 256, DYN_SMEM>>>(pAhi, pAlo, pWhi + 3 * (size_t)DM * DM,
                                       pWlo + 3 * (size_t)DM * DM, out);
}

// round 8
// speedup vs baseline: 4.1603x; 1.5049x over previous
#include <cuda_runtime.h>
#include <cuda_fp16.h>
#include <math.h>
#include <stdint.h>

typedef uint32_t u32; typedef uint64_t u64;

#define S_LEN 4096
#define B_SZ  2
#define DM    1024
#define NH    16
#define DK    64
#define RAD   8
#define WINW  9
#define M_TOT (B_SZ * S_LEN)
#define QT    64

// ---------------- scratch (device globals: allocation-free) ----------------
__device__ __half g_Xhi[M_TOT * DM];                      // x -> fp16 rn, [m][k]
__device__ __half g_Ahi[M_TOT * DM];                      // attn out -> fp16 rn, [m][k]
__device__ __half g_Whi[4][DM * DM], g_Wlo[4][DM * DM];   // W^T hi/lo, [n][k]
__device__ float  g_QKV[3][M_TOT * DM];                   // Q,K,V fp32

// ---------------- fp16 2-term tensor-core GEMM ----------------
// C = Ahi[m][k] @ (Bhi+Blo)[n][k]^T, fp32 accumulate.
// Dropped terms Alo*B (~2^-12 rel, unbiased) and lo*lo.
#define BM 128
#define BN 128
#define BK 64
#define NSTG 4
#define PLANE_B (128 * 128)          // bytes per plane per stage (128 rows x 128B)
#define STG_B   (3 * PLANE_B)        // Ahi,Bhi,Blo = 48 KB
#define DYN_SMEM (NSTG * STG_B)      // 192 KB

__device__ __forceinline__ void cp16(u32 dst, const void* src) {
    asm volatile("cp.async.cg.shared.global [%0], [%1], 16;" :: "r"(dst), "l"(src) : "memory");
}

#define LDMX4(r, addr)                                                        \
    asm volatile("ldmatrix.sync.aligned.m8n8.x4.shared.b16 {%0,%1,%2,%3}, [%4];" \
                 : "=r"((r)[0]), "=r"((r)[1]), "=r"((r)[2]), "=r"((r)[3])     \
                 : "r"(addr))

#define MMA16(c, a, b)                                                        \
    asm volatile("mma.sync.aligned.m16n8k16.row.col.f32.f16.f16.f32 "         \
                 "{%0,%1,%2,%3}, {%4,%5,%6,%7}, {%8,%9}, {%0,%1,%2,%3};"      \
                 : "+f"((c)[0]), "+f"((c)[1]), "+f"((c)[2]), "+f"((c)[3])     \
                 : "r"((a)[0]), "r"((a)[1]), "r"((a)[2]), "r"((a)[3]),        \
                   "r"((b)[0]), "r"((b)[1]))

// Fused over multiple weight matrices: which = blockIdx.x / nxb selects the
// weight planes (stride DM*DM) and the output buffer (stride M_TOT*DM).
__global__ __launch_bounds__(256, 1)
void gemm_fp16x2(const __half* __restrict__ Ahi,
                 const __half* __restrict__ WhiBase, const __half* __restrict__ WloBase,
                 float* __restrict__ CBase, int nxb) {
    extern __shared__ char smc[];
    const u32 s0 = (u32)__cvta_generic_to_shared(smc);
    const int tid = threadIdx.x, wid = tid >> 5, lane = tid & 31;
    const int wm = wid & 1, wn = wid >> 1;              // 2x4 warp grid: 64x32 per warp
    const int which = blockIdx.x / nxb;
    const int m0 = blockIdx.y * BM, n0 = (blockIdx.x % nxb) * BN;
    const int g = lane >> 2, tg = lane & 3;

    const __half* Bhi = WhiBase + (size_t)which * DM * DM;
    const __half* Blo = WloBase + (size_t)which * DM * DM;
    float* C = CBase + (size_t)which * M_TOT * DM;

    // cp.async plan: 3072 16B units/stage (3 planes x 1024), 12 per thread.
    // unit u: plane = u>>10, row = (u>>3)&127, chunk c = u&7; swizzle c^(row&7).
    u32 sdst[12]; const char* gsrc[12];
#pragma unroll
    for (int t = 0; t < 12; t++) {
        int u = tid + t * 256;
        int plane = u >> 10, row = (u >> 3) & 127, c = u & 7;
        sdst[t] = s0 + plane * PLANE_B + row * 128 + ((c ^ (row & 7)) * 16);
        const __half* bp = (plane == 0) ? Ahi : (plane == 1) ? Bhi : Blo;
        int grow = ((plane == 0) ? m0 : n0) + row;
        gsrc[t] = (const char*)(bp + (size_t)grow * DM) + c * 16;
    }

#define ISSUE(kidx) do {                                                      \
    u32 so = ((kidx) & (NSTG - 1)) * STG_B;                                   \
    _Pragma("unroll")                                                         \
    for (int t = 0; t < 12; t++)                                              \
        cp16(sdst[t] + so, gsrc[t] + (size_t)(kidx) * 128);                   \
    asm volatile("cp.async.commit_group;" ::: "memory");                      \
} while (0)

    ISSUE(0); ISSUE(1); ISSUE(2);

    float acc[4][4][4];
#pragma unroll
    for (int i = 0; i < 4; i++)
#pragma unroll
        for (int j = 0; j < 4; j++)
#pragma unroll
            for (int q = 0; q < 4; q++) acc[i][j][q] = 0.f;

    const int NIT = DM / BK;                            // 16
    const int rsel = lane & 15, csel = lane >> 4;

    for (int it = 0; it < NIT; it++) {
        asm volatile("cp.async.wait_group 2;" ::: "memory");
        __syncthreads();
        const u32 sb = s0 + (it & (NSTG - 1)) * STG_B;

#pragma unroll
        for (int j = 0; j < 4; j++) {                   // four k16 steps per BK=64
            u32 ahi[4][4], bhi[4][2], blo[4][2];
#pragma unroll
            for (int mt = 0; mt < 4; mt++) {
                int row = wm * 64 + mt * 16 + rsel;
                u32 ad = sb + row * 128 + (((2 * j + csel) ^ (row & 7)) * 16);
                LDMX4(ahi[mt], ad);
            }
#pragma unroll
            for (int np = 0; np < 2; np++) {            // each x4 covers two n8 tiles
                int row = wn * 32 + np * 16 + rsel;
                u32 bd = sb + PLANE_B + row * 128 + (((2 * j + csel) ^ (row & 7)) * 16);
                u32 r[4];
                LDMX4(r, bd);
                bhi[2*np][0] = r[0]; bhi[2*np+1][0] = r[1];
                bhi[2*np][1] = r[2]; bhi[2*np+1][1] = r[3];
                LDMX4(r, bd + PLANE_B);
                blo[2*np][0] = r[0]; blo[2*np+1][0] = r[1];
                blo[2*np][1] = r[2]; blo[2*np+1][1] = r[3];
            }
#pragma unroll
            for (int mt = 0; mt < 4; mt++)
#pragma unroll
                for (int nt = 0; nt < 4; nt++) {
                    MMA16(acc[mt][nt], ahi[mt], bhi[nt]);
                    MMA16(acc[mt][nt], ahi[mt], blo[nt]);
                }
        }
        __syncthreads();
        if (it + 3 < NIT) ISSUE(it + 3);
        else asm volatile("cp.async.commit_group;" ::: "memory");
    }

#pragma unroll
    for (int mt = 0; mt < 4; mt++)
#pragma unroll
        for (int nt = 0; nt < 4; nt++) {
            int row = m0 + wm * 64 + mt * 16 + g;
            int col = n0 + wn * 32 + nt * 8 + 2 * tg;
            float* p = C + (size_t)row * DM + col;
            *(float2*)p = make_float2(acc[mt][nt][0], acc[mt][nt][1]);
            *(float2*)(p + 8 * DM) = make_float2(acc[mt][nt][2], acc[mt][nt][3]);
        }
#undef ISSUE
}

// ---------------- x convert: fp32 -> fp16 rn (hi only) ----------------
__global__ void convert_x_k(const float* __restrict__ in, __half* __restrict__ hi) {
    int i = blockIdx.x * blockDim.x + threadIdx.x;
    float4 v = ((const float4*)in)[i];
    ((__half2*)hi)[2 * i]     = __halves2half2(__float2half_rn(v.x), __float2half_rn(v.y));
    ((__half2*)hi)[2 * i + 1] = __halves2half2(__float2half_rn(v.z), __float2half_rn(v.w));
}

// ---------------- W transpose + split: W[k][n] -> hi/lo [n][k] ----------------
__global__ void transpose_split_k(const float* __restrict__ W,
                                  __half* __restrict__ hi, __half* __restrict__ lo) {
    __shared__ float t[32][33];
    int bx = blockIdx.x * 32, by = blockIdx.y * 32;
    int x = threadIdx.x, y = threadIdx.y;
#pragma unroll
    for (int j = 0; j < 32; j += 8)
        t[y + j][x] = W[(size_t)(by + y + j) * DM + bx + x];
    __syncthreads();
#pragma unroll
    for (int j = 0; j < 32; j += 8) {
        float v = t[x][y + j];
        __half h = __float2half_rn(v);
        size_t o = (size_t)(bx + y + j) * DM + by + x;
        hi[o] = h;
        lo[o] = __float2half_rn(v - __half2float(h));
    }
}

// ---------------- windowed causal attention; epilogue emits fp16 hi ----------------
__global__ __launch_bounds__(256)
void attn_kernel(const float* __restrict__ Q, const float* __restrict__ K,
                 const float* __restrict__ V, __half* __restrict__ Ohi) {
    int qbase = blockIdx.x * QT;
    int h = blockIdx.y;
    int b = blockIdx.z;

    __shared__ __align__(16) float Ks[QT + RAD][DK];
    __shared__ __align__(16) float Vs[QT + RAD][DK];

    int tid = threadIdx.x;
    const size_t bh = (size_t)b * S_LEN * DM + (size_t)h * DK;
    int base = qbase - RAD;

    for (int idx = tid; idx < (QT + RAD) * (DK / 4); idx += blockDim.x) {
        int r = idx / (DK / 4);
        int cidx = (idx % (DK / 4)) * 4;
        int j = base + r;
        float4 kv = make_float4(0.f, 0.f, 0.f, 0.f), vv = kv;
        if (j >= 0) {
            kv = *(const float4*)(K + bh + (size_t)j * DM + cidx);
            vv = *(const float4*)(V + bh + (size_t)j * DM + cidx);
        }
        *(float4*)&Ks[r][cidx] = kv;
        *(float4*)&Vs[r][cidx] = vv;
    }
    __syncthreads();

    int warp = tid >> 5, lane = tid & 31;
    const float scale = 1.0f / 0.56f;   // 1/(2T), T=0.28

    for (int qi = 0; qi < QT / 8; qi++) {
        int sl = warp * (QT / 8) + qi;
        int s = qbase + sl;
        float q0 = Q[bh + (size_t)s * DM + lane];
        float q1 = Q[bh + (size_t)s * DM + lane + 32];

        float sc[WINW];
#pragma unroll
        for (int w = 0; w < WINW; w++) {
            int r = sl + w;
            float p = q0 * Ks[r][lane] + q1 * Ks[r][lane + 32];
#pragma unroll
            for (int o = 16; o > 0; o >>= 1)
                p += __shfl_xor_sync(0xffffffffu, p, o);
            sc[w] = (s - RAD + w >= 0) ? p * scale : -INFINITY;
        }

        float m = sc[0];
#pragma unroll
        for (int w = 1; w < WINW; w++) m = fmaxf(m, sc[w]);

        float sum = 0.f, a0 = 0.f, a1 = 0.f;
#pragma unroll
        for (int w = 0; w < WINW; w++) {
            float e = __expf(sc[w] - m);
            sum += e;
            int r = sl + w;
            a0 += e * Vs[r][lane];
            a1 += e * Vs[r][lane + 32];
        }
        float inv = 1.0f / sum;
        Ohi[bh + (size_t)s * DM + lane]      = __float2half_rn(a0 * inv);
        Ohi[bh + (size_t)s * DM + lane + 32] = __float2half_rn(a1 * inv);
    }
}

// ---------------- launch ----------------
extern "C" void kernel_launch(void* const* d_in, const int* in_sizes, int n_in,
                              void* d_out, int out_size) {
    const float* x  = (const float*)d_in[0];
    const float* Wq = (const float*)d_in[1];
    const float* Wk = (const float*)d_in[2];
    const float* Wv = (const float*)d_in[3];
    const float* Wo = (const float*)d_in[4];
    float* out = (float*)d_out;

    __half *pXhi, *pAhi, *pWhi, *pWlo;
    float *pQKV;
    cudaGetSymbolAddress((void**)&pXhi, g_Xhi);
    cudaGetSymbolAddress((void**)&pAhi, g_Ahi);
    cudaGetSymbolAddress((void**)&pWhi, g_Whi);
    cudaGetSymbolAddress((void**)&pWlo, g_Wlo);
    cudaGetSymbolAddress((void**)&pQKV, g_QKV);
    float* pQ = pQKV + 0 * (size_t)M_TOT * DM;
    float* pK = pQKV + 1 * (size_t)M_TOT * DM;
    float* pV = pQKV + 2 * (size_t)M_TOT * DM;

    cudaFuncSetAttribute(gemm_fp16x2, cudaFuncAttributeMaxDynamicSharedMemorySize, DYN_SMEM);

    convert_x_k<<<(M_TOT * DM / 4) / 256, 256>>>(x, pXhi);

    dim3 tg(DM / 32, DM / 32), tb(32, 8);
    const float* Ws[4] = {Wq, Wk, Wv, Wo};
    for (int i = 0; i < 4; i++)
        transpose_split_k<<<tg, tb>>>(Ws[i], pWhi + (size_t)i * DM * DM,
                                      pWlo + (size_t)i * DM * DM);

    // fused QKV: grid.x = 3 weights x 8 n-blocks
    dim3 gqkv(3 * (DM / BN), M_TOT / BM);
    gemm_fp16x2<<<gqkv, 256, DYN_SMEM>>>(pXhi, pWhi, pWlo, pQKV, DM / BN);

    dim3 ga(S_LEN / QT, NH, B_SZ);
    attn_kernel<<<ga, 256>>>(pQ, pK, pV, pAhi);

    // output projection: weight index 3
    dim3 go(DM / BN, M_TOT / BM);
    gemm_fp16x2<<<go, 256, DYN_SMEM>>>(pAhi, pWhi + 3 * (size_t)DM * DM,
                                       pWlo + 3 * (size_t)DM * DM, out, DM / BN);
}